// round 12
// baseline (speedup 1.0000x reference)
#include <cuda_runtime.h>
#include <cuda_fp16.h>
#include <cstdint>
#include <cstddef>

#define NROWS   1024
#define MROWS   (NROWS*NROWS)
#define FIN     128
#define FHID    64
#define EPSV    1e-5f
#define ALPHAV  0.2f
#define NEGV    -9e15f

#define BSTRIDE 136   // B k-stride in fp16 (272B rows)
#define ASTR2   40    // A k-stride in fp16 (80B rows), K=32 phase tile

// ---------------- device scratch ----------------
__device__ __align__(16) float g_S1[FIN];
__device__ __align__(16) float g_Q1[FIN];
__device__ __align__(16) float g_cvec[FHID];
__device__ __align__(16) float g_S2[FHID];
__device__ __align__(16) float g_Q2[FHID];
__device__ __align__(16) float g_p[FHID];
__device__ __align__(16) float g_q[FHID];
__device__ __align__(16) float g_S3[2];
__device__ __align__(16) float g_s3b3[2];
__device__ __align__(16) __half g_Bh[FHID*BSTRIDE];         // fp16 W1 [n][k] padded
__device__ __align__(16) uint4 g_Ah[(size_t)MROWS*16];      // 256MB fp16-hi plane [row][128]
__device__ __align__(16) uint4 g_Al[(size_t)MROWS*16];      // 256MB fp16-lo plane
__device__ __align__(16) float g_ybuf[(size_t)MROWS*FHID];  // 256MB
__device__ __align__(16) float g_zbuf[MROWS];

__device__ __forceinline__ float leakyf(float x){ return x >= 0.f ? x : ALPHAV*x; }

__device__ __forceinline__ uint32_t smem_u32(const void* p){
    uint32_t a;
    asm("{ .reg .u64 t; cvta.to.shared.u64 t, %1; cvt.u32.u64 %0, t; }" : "=r"(a) : "l"(p));
    return a;
}
__device__ __forceinline__ void ldm_x4(uint32_t* r, uint32_t addr){
    asm volatile("ldmatrix.sync.aligned.m8n8.x4.shared.b16 {%0,%1,%2,%3}, [%4];"
                 : "=r"(r[0]), "=r"(r[1]), "=r"(r[2]), "=r"(r[3]) : "r"(addr));
}
__device__ __forceinline__ void mma_f16(float* c, const uint32_t* a, const uint32_t* b){
    asm volatile("mma.sync.aligned.m16n8k16.row.col.f32.f16.f16.f32 "
        "{%0,%1,%2,%3}, {%4,%5,%6,%7}, {%8,%9}, {%0,%1,%2,%3};"
        : "+f"(c[0]), "+f"(c[1]), "+f"(c[2]), "+f"(c[3])
        : "r"(a[0]), "r"(a[1]), "r"(a[2]), "r"(a[3]), "r"(b[0]), "r"(b[1]));
}

// ---------------- K0 ----------------
__global__ void k_zero(){
    int t = threadIdx.x;
    if (t < FIN){ g_S1[t]=0.f; g_Q1[t]=0.f; }
    if (t < FHID){ g_S2[t]=0.f; g_Q2[t]=0.f; }
    if (t < 2) g_S3[t]=0.f;
}

// ---------------- K1: col stats of adj + fused fp16 hi/lo split ------------------
__global__ __launch_bounds__(256) void k_colstats(const float* __restrict__ adj){
    const int lane = threadIdx.x & 31;
    const int warp = (blockIdx.x*blockDim.x + threadIdx.x) >> 5;
    const int nw   = (gridDim.x*blockDim.x) >> 5;
    uint2* planeH = reinterpret_cast<uint2*>(g_Ah);
    uint2* planeL = reinterpret_cast<uint2*>(g_Al);
    float s0=0.f,s1=0.f,s2=0.f,s3=0.f,q0=0.f,q1=0.f,q2=0.f,q3=0.f;
    for (int r = warp*8; r < MROWS; r += nw*8){
        float4 v[8];
        #pragma unroll
        for (int i = 0; i < 8; i++)
            v[i] = *reinterpret_cast<const float4*>(adj + (size_t)(r+i)*FIN + lane*4);
        #pragma unroll
        for (int i = 0; i < 8; i++){
            s0+=v[i].x; q0+=v[i].x*v[i].x;
            s1+=v[i].y; q1+=v[i].y*v[i].y;
            s2+=v[i].z; q2+=v[i].z*v[i].z;
            s3+=v[i].w; q3+=v[i].w*v[i].w;
            __half2 h01 = __floats2half2_rn(v[i].x, v[i].y);
            __half2 h23 = __floats2half2_rn(v[i].z, v[i].w);
            float rx = v[i].x - __low2float(h01);
            float ry = v[i].y - __high2float(h01);
            float rz = v[i].z - __low2float(h23);
            float rw = v[i].w - __high2float(h23);
            __half2 l01 = __floats2half2_rn(rx, ry);
            __half2 l23 = __floats2half2_rn(rz, rw);
            planeH[(size_t)(r+i)*32 + lane] =
                make_uint2(*reinterpret_cast<uint32_t*>(&h01), *reinterpret_cast<uint32_t*>(&h23));
            planeL[(size_t)(r+i)*32 + lane] =
                make_uint2(*reinterpret_cast<uint32_t*>(&l01), *reinterpret_cast<uint32_t*>(&l23));
        }
    }
    __shared__ float bs[FIN], bq[FIN];
    if (threadIdx.x < FIN){ bs[threadIdx.x]=0.f; bq[threadIdx.x]=0.f; }
    __syncthreads();
    atomicAdd(&bs[lane*4+0], s0); atomicAdd(&bs[lane*4+1], s1);
    atomicAdd(&bs[lane*4+2], s2); atomicAdd(&bs[lane*4+3], s3);
    atomicAdd(&bq[lane*4+0], q0); atomicAdd(&bq[lane*4+1], q1);
    atomicAdd(&bq[lane*4+2], q2); atomicAdd(&bq[lane*4+3], q3);
    __syncthreads();
    if (threadIdx.x < FIN){
        atomicAdd(&g_S1[threadIdx.x], bs[threadIdx.x]);
        atomicAdd(&g_Q1[threadIdx.x], bq[threadIdx.x]);
    }
}

// ---------------- K2: fold BN1 into W -> single fp16 image [n][k] ----------------
__global__ void k_fold1(const float* __restrict__ W,
                        const float* __restrict__ gamma1,
                        const float* __restrict__ beta1){
    __shared__ float s1s[FIN], b1s[FIN];
    int t = threadIdx.x;
    if (t < FIN){
        float mu  = g_S1[t] * (1.f/(float)MROWS);
        float var = g_Q1[t] * (1.f/(float)MROWS) - mu*mu;
        float sc  = gamma1[t] * rsqrtf(var + EPSV);
        s1s[t] = sc;
        b1s[t] = beta1[t] - mu*sc;
    }
    __syncthreads();
    for (int i = t; i < FIN*FHID; i += blockDim.x){
        int k = i >> 6, n = i & 63;
        float w1 = s1s[k] * W[i];
        g_Bh[n*BSTRIDE + k] = __float2half_rn(w1);
    }
    if (t < FHID){
        float acc = 0.f;
        for (int j = 0; j < FIN; j++) acc += b1s[j] * W[j*FHID + t];
        g_cvec[t] = acc;
    }
}

// ---------------- K3: HMMA fp16 2-term GEMM, 256-row CTA, 2/SM, cp.async pipe ---
// dyn smem: AH0(20480) AH1(20480) AL0(20480) AL1(20480) BH(17408) = 99328
#define SOFF_AH0 0
#define ABUF_SZ  20480
#define AHL_OFF  40960          // AL(b) = AH(b) + AHL_OFF
#define SOFF_BH  81920
#define SMEM_TOT 99328

__device__ __forceinline__ void stage_phase(uint32_t dstH, int row0, int t, int ph){
    const uint32_t dstL = dstH + AHL_OFF;
    #pragma unroll
    for (int i = 0; i < 4; i++){
        int idx = t + i*256;          // 0..1023
        int r = idx >> 2, c = idx & 3;
        size_t gidx = (size_t)(row0 + r)*16 + (size_t)(ph*4 + c);
        uint32_t so = (uint32_t)(r*(ASTR2*2) + c*16);
        asm volatile("cp.async.cg.shared.global [%0], [%1], 16;"
            :: "r"(dstH + so), "l"(g_Ah + gidx) : "memory");
        asm volatile("cp.async.cg.shared.global [%0], [%1], 16;"
            :: "r"(dstL + so), "l"(g_Al + gidx) : "memory");
    }
}

__global__ void __launch_bounds__(256, 2) k_gemm(){
    extern __shared__ __align__(1024) char smem[];
    const uint32_t sb = smem_u32(smem);
    const int t = threadIdx.x;
    const int w = t >> 5, lane = t & 31;
    const int g  = lane >> 2, tc = lane & 3;
    const int row0 = blockIdx.x * 256;

    __shared__ float cs[FHID], cq[FHID];
    if (t < FHID){ cs[t]=0.f; cq[t]=0.f; }

    // prologue: issue phase-0 A copy
    stage_phase(sb + SOFF_AH0, row0, t, 0);
    asm volatile("cp.async.commit_group;" ::: "memory");

    // B: flat copy of prebuilt fp16 image (1088 uint4)
    {
        const uint4* sh = reinterpret_cast<const uint4*>(g_Bh);
        uint4* dh = reinterpret_cast<uint4*>(smem + SOFF_BH);
        #pragma unroll
        for (int i = 0; i < 5; i++){
            int idx = t + i*256;
            if (idx < 1088) dh[idx] = sh[idx];
        }
    }

    // fragment base offsets: warp w owns rows w*32..w*32+31 (2 m-tiles of 16)
    const uint32_t aOffBase =
        (uint32_t)((w*32 + (lane & 15))*(ASTR2*2) + (lane >> 4)*16);
    const uint32_t bBase = sb + SOFF_BH +
        (uint32_t)(((lane & 7) + ((lane & 16) >> 1))*BSTRIDE + (lane & 8))*2u;

    float acc[2][8][4];
    #pragma unroll
    for (int mt = 0; mt < 2; mt++)
        #pragma unroll
        for (int nt = 0; nt < 8; nt++)
            #pragma unroll
            for (int i = 0; i < 4; i++) acc[mt][nt][i] = 0.f;

    #pragma unroll
    for (int ph = 0; ph < 4; ph++){
        asm volatile("cp.async.wait_group 0;" ::: "memory");
        __syncthreads();
        if (ph < 3){
            stage_phase(sb + SOFF_AH0 + ((ph+1)&1)*ABUF_SZ, row0, t, ph+1);
            asm volatile("cp.async.commit_group;" ::: "memory");
        }
        const uint32_t aBase = sb + SOFF_AH0 + (ph&1)*ABUF_SZ + aOffBase;
        #pragma unroll
        for (int ksl = 0; ksl < 2; ksl++){
            const uint32_t kA = (uint32_t)(ksl*32);            // 16 fp16 = 32B
            const uint32_t kB = (uint32_t)((ph*2 + ksl)*32);
            uint32_t ah0[4], al0[4], ah1[4], al1[4];
            ldm_x4(ah0, aBase + kA);
            ldm_x4(al0, aBase + kA + AHL_OFF);
            ldm_x4(ah1, aBase + kA + (uint32_t)(16*ASTR2*2));
            ldm_x4(al1, aBase + kA + (uint32_t)(16*ASTR2*2) + AHL_OFF);
            #pragma unroll
            for (int p = 0; p < 4; p++){
                const uint32_t bo = bBase + kB + (uint32_t)(p*16*BSTRIDE*2);
                uint32_t bh[4];
                ldm_x4(bh, bo);
                // 2-term fp16 split: (ah + al) @ bh, mt-interleaved
                mma_f16(acc[0][2*p],   ah0, bh);
                mma_f16(acc[1][2*p],   ah1, bh);
                mma_f16(acc[0][2*p+1], ah0, bh+2);
                mma_f16(acc[1][2*p+1], ah1, bh+2);
                mma_f16(acc[0][2*p],   al0, bh);
                mma_f16(acc[1][2*p],   al1, bh);
                mma_f16(acc[0][2*p+1], al0, bh+2);
                mma_f16(acc[1][2*p+1], al1, bh+2);
            }
        }
    }

    // epilogue: per n-tile — add cvec, write y (4 rows/thread), one reduce
    #pragma unroll
    for (int nt = 0; nt < 8; nt++){
        const int c0 = nt*8 + 2*tc;
        const float cv0 = __ldg(&g_cvec[c0]);
        const float cv1 = __ldg(&g_cvec[c0+1]);
        float s0 = 0.f, q0 = 0.f, s1 = 0.f, q1 = 0.f;
        #pragma unroll
        for (int mt = 0; mt < 2; mt++){
            const int r0 = row0 + w*32 + mt*16 + g;
            const int r1 = r0 + 8;
            float v00 = acc[mt][nt][0] + cv0;
            float v01 = acc[mt][nt][1] + cv1;
            float v10 = acc[mt][nt][2] + cv0;
            float v11 = acc[mt][nt][3] + cv1;
            *reinterpret_cast<float2*>(&g_ybuf[(size_t)r0*FHID + c0]) = make_float2(v00, v01);
            *reinterpret_cast<float2*>(&g_ybuf[(size_t)r1*FHID + c0]) = make_float2(v10, v11);
            s0 += v00 + v10;  q0 += v00*v00 + v10*v10;
            s1 += v01 + v11;  q1 += v01*v01 + v11*v11;
        }
        #pragma unroll
        for (int o = 4; o <= 16; o <<= 1){
            s0 += __shfl_xor_sync(0xffffffffu, s0, o);
            q0 += __shfl_xor_sync(0xffffffffu, q0, o);
            s1 += __shfl_xor_sync(0xffffffffu, s1, o);
            q1 += __shfl_xor_sync(0xffffffffu, q1, o);
        }
        if (lane < 4){
            atomicAdd(&cs[c0  ], s0);
            atomicAdd(&cq[c0  ], q0);
            atomicAdd(&cs[c0+1], s1);
            atomicAdd(&cq[c0+1], q1);
        }
    }
    __syncthreads();
    if (t < FHID){
        atomicAdd(&g_S2[t], cs[t]);
        atomicAdd(&g_Q2[t], cq[t]);
    }
}

// ---------------- K4 ----------------
__global__ void k_fold2(const float* __restrict__ gamma2, const float* __restrict__ beta2){
    int t = threadIdx.x;
    if (t < FHID){
        float mu  = g_S2[t] * (1.f/(float)MROWS);
        float var = g_Q2[t] * (1.f/(float)MROWS) - mu*mu;
        float sc  = gamma2[t] * rsqrtf(var + EPSV);
        g_p[t] = sc;
        g_q[t] = beta2[t] - mu*sc;
    }
}

// ---------------- K5: z pass ----------------
__global__ __launch_bounds__(256) void k_zpass(const float* __restrict__ avec){
    const int t    = threadIdx.x;
    const int lane = t & 31;
    const int g    = lane & 7;
    float pc[8], qc[8], ac[8];
    #pragma unroll
    for (int i = 0; i < 4; i++){
        pc[i]   = g_p[g*4+i];      qc[i]   = g_q[g*4+i];      ac[i]   = avec[g*4+i];
        pc[4+i] = g_p[32+g*4+i];   qc[4+i] = g_q[32+g*4+i];   ac[4+i] = avec[32+g*4+i];
    }
    const int warp = (blockIdx.x*blockDim.x + t) >> 5;
    const int nw   = (gridDim.x*blockDim.x) >> 5;
    float zs = 0.f, zq = 0.f;
    for (int base = warp*8; base < MROWS; base += nw*8){
        #pragma unroll
        for (int h = 0; h < 2; h++){
            int row = base + h*4 + (lane >> 3);
            const float4 v0 = *reinterpret_cast<const float4*>(&g_ybuf[(size_t)row*FHID + g*4]);
            const float4 v1 = *reinterpret_cast<const float4*>(&g_ybuf[(size_t)row*FHID + 32 + g*4]);
            float z = 0.f;
            z += leakyf(v0.x*pc[0]+qc[0])*ac[0];
            z += leakyf(v0.y*pc[1]+qc[1])*ac[1];
            z += leakyf(v0.z*pc[2]+qc[2])*ac[2];
            z += leakyf(v0.w*pc[3]+qc[3])*ac[3];
            z += leakyf(v1.x*pc[4]+qc[4])*ac[4];
            z += leakyf(v1.y*pc[5]+qc[5])*ac[5];
            z += leakyf(v1.z*pc[6]+qc[6])*ac[6];
            z += leakyf(v1.w*pc[7]+qc[7])*ac[7];
            z += __shfl_xor_sync(0xffffffffu, z, 1);
            z += __shfl_xor_sync(0xffffffffu, z, 2);
            z += __shfl_xor_sync(0xffffffffu, z, 4);
            if (g == 0){
                g_zbuf[row] = z;
                zs += z; zq += z*z;
            }
        }
    }
    #pragma unroll
    for (int o = 16; o > 0; o >>= 1){
        zs += __shfl_xor_sync(0xffffffffu, zs, o);
        zq += __shfl_xor_sync(0xffffffffu, zq, o);
    }
    if (lane == 0){
        atomicAdd(&g_S3[0], zs);
        atomicAdd(&g_S3[1], zq);
    }
}

// ---------------- K6 ----------------
__global__ void k_fold3(const float* __restrict__ gamma3, const float* __restrict__ beta3){
    float mu  = g_S3[0] * (1.f/(float)MROWS);
    float var = g_S3[1] * (1.f/(float)MROWS) - mu*mu;
    float sc  = gamma3[0] * rsqrtf(var + EPSV);
    g_s3b3[0] = sc;
    g_s3b3[1] = beta3[0] - mu*sc;
}

// ---------------- K7: masked row softmax ----------------
__global__ __launch_bounds__(256) void k_softmax(const float* __restrict__ adj_mean,
                                                 float* __restrict__ out){
    const int row = blockIdx.x;
    const int t   = threadIdx.x;
    const int lane = t & 31, wid = t >> 5;
    const float s3 = g_s3b3[0], b3 = g_s3b3[1];

    const float4 zv = *reinterpret_cast<const float4*>(&g_zbuf[(size_t)row*NROWS + t*4]);
    const float4 mv = *reinterpret_cast<const float4*>(&adj_mean[(size_t)row*NROWS + t*4]);
    float v[4];
    {
        float zz[4] = {zv.x, zv.y, zv.z, zv.w};
        float mm[4] = {mv.x, mv.y, mv.z, mv.w};
        #pragma unroll
        for (int i = 0; i < 4; i++){
            float e = leakyf(zz[i]*s3 + b3);
            v[i] = (mm[i] > 0.f) ? e : NEGV;
        }
    }
    __shared__ float sred[8];
    float mx = fmaxf(fmaxf(v[0],v[1]), fmaxf(v[2],v[3]));
    #pragma unroll
    for (int o = 16; o > 0; o >>= 1) mx = fmaxf(mx, __shfl_xor_sync(0xffffffffu, mx, o));
    if (lane == 0) sred[wid] = mx;
    __syncthreads();
    if (t < 32){
        float m2 = (t < 8) ? sred[t] : -3.4e38f;
        #pragma unroll
        for (int o = 4; o > 0; o >>= 1) m2 = fmaxf(m2, __shfl_xor_sync(0xffffffffu, m2, o));
        if (t == 0) sred[0] = m2;
    }
    __syncthreads();
    mx = sred[0];
    __syncthreads();
    float e[4];
    #pragma unroll
    for (int i = 0; i < 4; i++) e[i] = __expf(v[i] - mx);
    float se = e[0]+e[1]+e[2]+e[3];
    #pragma unroll
    for (int o = 16; o > 0; o >>= 1) se += __shfl_xor_sync(0xffffffffu, se, o);
    if (lane == 0) sred[wid] = se;
    __syncthreads();
    if (t < 32){
        float s2 = (t < 8) ? sred[t] : 0.f;
        #pragma unroll
        for (int o = 4; o > 0; o >>= 1) s2 += __shfl_xor_sync(0xffffffffu, s2, o);
        if (t == 0) sred[0] = s2;
    }
    __syncthreads();
    const float inv = 1.f / sred[0];
    float4 ov = make_float4(e[0]*inv, e[1]*inv, e[2]*inv, e[3]*inv);
    *reinterpret_cast<float4*>(&out[(size_t)row*NROWS + t*4]) = ov;
}

// ---------------- launch ----------------
extern "C" void kernel_launch(void* const* d_in, const int* in_sizes, int n_in,
                              void* d_out, int out_size){
    const float* adj      = (const float*)d_in[0];
    const float* adj_mean = (const float*)d_in[1];
    const float* W        = (const float*)d_in[2];
    const float* a        = (const float*)d_in[3];
    const float* gamma1   = (const float*)d_in[4];
    const float* beta1    = (const float*)d_in[5];
    const float* gamma2   = (const float*)d_in[6];
    const float* beta2    = (const float*)d_in[7];
    const float* gamma3   = (const float*)d_in[8];
    const float* beta3    = (const float*)d_in[9];
    float* out = (float*)d_out;

    cudaFuncSetAttribute(k_gemm, cudaFuncAttributeMaxDynamicSharedMemorySize, SMEM_TOT);

    k_zero    <<<1, 128>>>();
    k_colstats<<<4096, 256>>>(adj);
    k_fold1   <<<1, 256>>>(W, gamma1, beta1);
    k_gemm    <<<MROWS/256, 256, SMEM_TOT>>>();
    k_fold2   <<<1, 64>>>(gamma2, beta2);
    k_zpass   <<<2048, 256>>>(a);
    k_fold3   <<<1, 1>>>(gamma3, beta3);
    k_softmax <<<NROWS, 256>>>(adj_mean, out);
}

// round 13
// speedup vs baseline: 1.3110x; 1.3110x over previous
#include <cuda_runtime.h>
#include <cuda_fp16.h>
#include <cstdint>
#include <cstddef>

#define NROWS   1024
#define MROWS   (NROWS*NROWS)
#define FIN     128
#define FHID    64
#define EPSV    1e-5f
#define ALPHAV  0.2f
#define NEGV    -9e15f

#define BSTRIDE 136   // B k-stride in fp16 (272B rows)
#define ASTR2   40    // A k-stride in fp16 (80B rows), K=32 phase tile

// ---------------- device scratch ----------------
__device__ __align__(16) float g_S1[FIN];
__device__ __align__(16) float g_Q1[FIN];
__device__ __align__(16) float g_cvec[FHID];
__device__ __align__(16) float g_S2[FHID];
__device__ __align__(16) float g_Q2[FHID];
__device__ __align__(16) float g_p[FHID];
__device__ __align__(16) float g_q[FHID];
__device__ __align__(16) float g_S3[2];
__device__ __align__(16) float g_s3b3[2];
__device__ __align__(16) __half g_Bh[FHID*BSTRIDE];         // fp16 W1 [n][k] padded
__device__ __align__(16) uint4 g_Ah[(size_t)MROWS*16];      // 256MB fp16 plane [row][128]
__device__ __align__(16) __half2 g_yh[(size_t)MROWS*32];    // 128MB fp16 y [row][64]
__device__ __align__(16) float g_zbuf[MROWS];

__device__ __forceinline__ float leakyf(float x){ return x >= 0.f ? x : ALPHAV*x; }

__device__ __forceinline__ uint32_t smem_u32(const void* p){
    uint32_t a;
    asm("{ .reg .u64 t; cvta.to.shared.u64 t, %1; cvt.u32.u64 %0, t; }" : "=r"(a) : "l"(p));
    return a;
}
__device__ __forceinline__ void ldm_x4(uint32_t* r, uint32_t addr){
    asm volatile("ldmatrix.sync.aligned.m8n8.x4.shared.b16 {%0,%1,%2,%3}, [%4];"
                 : "=r"(r[0]), "=r"(r[1]), "=r"(r[2]), "=r"(r[3]) : "r"(addr));
}
__device__ __forceinline__ void mma_f16(float* c, const uint32_t* a, const uint32_t* b){
    asm volatile("mma.sync.aligned.m16n8k16.row.col.f32.f16.f16.f32 "
        "{%0,%1,%2,%3}, {%4,%5,%6,%7}, {%8,%9}, {%0,%1,%2,%3};"
        : "+f"(c[0]), "+f"(c[1]), "+f"(c[2]), "+f"(c[3])
        : "r"(a[0]), "r"(a[1]), "r"(a[2]), "r"(a[3]), "r"(b[0]), "r"(b[1]));
}

// ---------------- K0 ----------------
__global__ void k_zero(){
    int t = threadIdx.x;
    if (t < FIN){ g_S1[t]=0.f; g_Q1[t]=0.f; }
    if (t < FHID){ g_S2[t]=0.f; g_Q2[t]=0.f; }
    if (t < 2) g_S3[t]=0.f;
}

// ---------------- K1: col stats of adj + fused single-fp16 conversion ------------
__global__ __launch_bounds__(256) void k_colstats(const float* __restrict__ adj){
    const int lane = threadIdx.x & 31;
    const int warp = (blockIdx.x*blockDim.x + threadIdx.x) >> 5;
    const int nw   = (gridDim.x*blockDim.x) >> 5;
    uint2* planeH = reinterpret_cast<uint2*>(g_Ah);
    float s0=0.f,s1=0.f,s2=0.f,s3=0.f,q0=0.f,q1=0.f,q2=0.f,q3=0.f;
    for (int r = warp*8; r < MROWS; r += nw*8){
        float4 v[8];
        #pragma unroll
        for (int i = 0; i < 8; i++)
            v[i] = *reinterpret_cast<const float4*>(adj + (size_t)(r+i)*FIN + lane*4);
        #pragma unroll
        for (int i = 0; i < 8; i++){
            s0+=v[i].x; q0+=v[i].x*v[i].x;
            s1+=v[i].y; q1+=v[i].y*v[i].y;
            s2+=v[i].z; q2+=v[i].z*v[i].z;
            s3+=v[i].w; q3+=v[i].w*v[i].w;
            __half2 h01 = __floats2half2_rn(v[i].x, v[i].y);
            __half2 h23 = __floats2half2_rn(v[i].z, v[i].w);
            planeH[(size_t)(r+i)*32 + lane] =
                make_uint2(*reinterpret_cast<uint32_t*>(&h01), *reinterpret_cast<uint32_t*>(&h23));
        }
    }
    __shared__ float bs[FIN], bq[FIN];
    if (threadIdx.x < FIN){ bs[threadIdx.x]=0.f; bq[threadIdx.x]=0.f; }
    __syncthreads();
    atomicAdd(&bs[lane*4+0], s0); atomicAdd(&bs[lane*4+1], s1);
    atomicAdd(&bs[lane*4+2], s2); atomicAdd(&bs[lane*4+3], s3);
    atomicAdd(&bq[lane*4+0], q0); atomicAdd(&bq[lane*4+1], q1);
    atomicAdd(&bq[lane*4+2], q2); atomicAdd(&bq[lane*4+3], q3);
    __syncthreads();
    if (threadIdx.x < FIN){
        atomicAdd(&g_S1[threadIdx.x], bs[threadIdx.x]);
        atomicAdd(&g_Q1[threadIdx.x], bq[threadIdx.x]);
    }
}

// ---------------- K2: fold BN1 into W -> single fp16 image [n][k] ----------------
__global__ void k_fold1(const float* __restrict__ W,
                        const float* __restrict__ gamma1,
                        const float* __restrict__ beta1){
    __shared__ float s1s[FIN], b1s[FIN];
    int t = threadIdx.x;
    if (t < FIN){
        float mu  = g_S1[t] * (1.f/(float)MROWS);
        float var = g_Q1[t] * (1.f/(float)MROWS) - mu*mu;
        float sc  = gamma1[t] * rsqrtf(var + EPSV);
        s1s[t] = sc;
        b1s[t] = beta1[t] - mu*sc;
    }
    __syncthreads();
    for (int i = t; i < FIN*FHID; i += blockDim.x){
        int k = i >> 6, n = i & 63;
        float w1 = s1s[k] * W[i];
        g_Bh[n*BSTRIDE + k] = __float2half_rn(w1);
    }
    if (t < FHID){
        float acc = 0.f;
        for (int j = 0; j < FIN; j++) acc += b1s[j] * W[j*FHID + t];
        g_cvec[t] = acc;
    }
}

// ---------------- K3: HMMA fp16 1-term GEMM, 256-row CTA, 2/SM, cp.async pipe ---
// dyn smem: AH0(20480) AH1(20480) BH(17408) = 58368
#define SOFF_AH0 0
#define ABUF_SZ  20480
#define SOFF_BH  40960
#define SMEM_TOT 58368

__device__ __forceinline__ void stage_phase(uint32_t dstH, int row0, int t, int ph){
    #pragma unroll
    for (int i = 0; i < 4; i++){
        int idx = t + i*256;          // 0..1023
        int r = idx >> 2, c = idx & 3;
        size_t gidx = (size_t)(row0 + r)*16 + (size_t)(ph*4 + c);
        uint32_t so = (uint32_t)(r*(ASTR2*2) + c*16);
        asm volatile("cp.async.cg.shared.global [%0], [%1], 16;"
            :: "r"(dstH + so), "l"(g_Ah + gidx) : "memory");
    }
}

__global__ void __launch_bounds__(256, 2) k_gemm(){
    extern __shared__ __align__(1024) char smem[];
    const uint32_t sb = smem_u32(smem);
    const int t = threadIdx.x;
    const int w = t >> 5, lane = t & 31;
    const int g  = lane >> 2, tc = lane & 3;
    const int row0 = blockIdx.x * 256;

    __shared__ float cs[FHID], cq[FHID];
    if (t < FHID){ cs[t]=0.f; cq[t]=0.f; }

    // prologue: issue phase-0 A copy
    stage_phase(sb + SOFF_AH0, row0, t, 0);
    asm volatile("cp.async.commit_group;" ::: "memory");

    // B: flat copy of prebuilt fp16 image (1088 uint4)
    {
        const uint4* sh = reinterpret_cast<const uint4*>(g_Bh);
        uint4* dh = reinterpret_cast<uint4*>(smem + SOFF_BH);
        #pragma unroll
        for (int i = 0; i < 5; i++){
            int idx = t + i*256;
            if (idx < 1088) dh[idx] = sh[idx];
        }
    }

    // fragment base offsets: warp w owns rows w*32..w*32+31 (2 m-tiles of 16)
    const uint32_t aOffBase =
        (uint32_t)((w*32 + (lane & 15))*(ASTR2*2) + (lane >> 4)*16);
    const uint32_t bBase = sb + SOFF_BH +
        (uint32_t)(((lane & 7) + ((lane & 16) >> 1))*BSTRIDE + (lane & 8))*2u;

    float acc[2][8][4];
    #pragma unroll
    for (int mt = 0; mt < 2; mt++)
        #pragma unroll
        for (int nt = 0; nt < 8; nt++)
            #pragma unroll
            for (int i = 0; i < 4; i++) acc[mt][nt][i] = 0.f;

    #pragma unroll
    for (int ph = 0; ph < 4; ph++){
        asm volatile("cp.async.wait_group 0;" ::: "memory");
        __syncthreads();
        if (ph < 3){
            stage_phase(sb + SOFF_AH0 + ((ph+1)&1)*ABUF_SZ, row0, t, ph+1);
            asm volatile("cp.async.commit_group;" ::: "memory");
        }
        const uint32_t aBase = sb + SOFF_AH0 + (ph&1)*ABUF_SZ + aOffBase;
        #pragma unroll
        for (int ksl = 0; ksl < 2; ksl++){
            const uint32_t kA = (uint32_t)(ksl*32);            // 16 fp16 = 32B
            const uint32_t kB = (uint32_t)((ph*2 + ksl)*32);
            uint32_t ah0[4], ah1[4];
            ldm_x4(ah0, aBase + kA);
            ldm_x4(ah1, aBase + kA + (uint32_t)(16*ASTR2*2));
            #pragma unroll
            for (int p = 0; p < 4; p++){
                const uint32_t bo = bBase + kB + (uint32_t)(p*16*BSTRIDE*2);
                uint32_t bh[4];
                ldm_x4(bh, bo);
                mma_f16(acc[0][2*p],   ah0, bh);
                mma_f16(acc[1][2*p],   ah1, bh);
                mma_f16(acc[0][2*p+1], ah0, bh+2);
                mma_f16(acc[1][2*p+1], ah1, bh+2);
            }
        }
    }

    // epilogue: per n-tile — add cvec, round to fp16, store y, stats from rounded
    #pragma unroll
    for (int nt = 0; nt < 8; nt++){
        const int c0 = nt*8 + 2*tc;
        const float cv0 = __ldg(&g_cvec[c0]);
        const float cv1 = __ldg(&g_cvec[c0+1]);
        float s0 = 0.f, q0 = 0.f, s1 = 0.f, q1 = 0.f;
        #pragma unroll
        for (int mt = 0; mt < 2; mt++){
            const int r0 = row0 + w*32 + mt*16 + g;
            const int r1 = r0 + 8;
            __half2 h0 = __floats2half2_rn(acc[mt][nt][0] + cv0, acc[mt][nt][1] + cv1);
            __half2 h1 = __floats2half2_rn(acc[mt][nt][2] + cv0, acc[mt][nt][3] + cv1);
            g_yh[(size_t)r0*32 + nt*4 + tc] = h0;
            g_yh[(size_t)r1*32 + nt*4 + tc] = h1;
            float2 f0 = __half22float2(h0);
            float2 f1 = __half22float2(h1);
            s0 += f0.x + f1.x;  q0 += f0.x*f0.x + f1.x*f1.x;
            s1 += f0.y + f1.y;  q1 += f0.y*f0.y + f1.y*f1.y;
        }
        #pragma unroll
        for (int o = 4; o <= 16; o <<= 1){
            s0 += __shfl_xor_sync(0xffffffffu, s0, o);
            q0 += __shfl_xor_sync(0xffffffffu, q0, o);
            s1 += __shfl_xor_sync(0xffffffffu, s1, o);
            q1 += __shfl_xor_sync(0xffffffffu, q1, o);
        }
        if (lane < 4){
            atomicAdd(&cs[c0  ], s0);
            atomicAdd(&cq[c0  ], q0);
            atomicAdd(&cs[c0+1], s1);
            atomicAdd(&cq[c0+1], q1);
        }
    }
    __syncthreads();
    if (t < FHID){
        atomicAdd(&g_S2[t], cs[t]);
        atomicAdd(&g_Q2[t], cq[t]);
    }
}

// ---------------- K4 ----------------
__global__ void k_fold2(const float* __restrict__ gamma2, const float* __restrict__ beta2){
    int t = threadIdx.x;
    if (t < FHID){
        float mu  = g_S2[t] * (1.f/(float)MROWS);
        float var = g_Q2[t] * (1.f/(float)MROWS) - mu*mu;
        float sc  = gamma2[t] * rsqrtf(var + EPSV);
        g_p[t] = sc;
        g_q[t] = beta2[t] - mu*sc;
    }
}

// ---------------- K5: z pass (fp16 y) ----------------
__global__ __launch_bounds__(256) void k_zpass(const float* __restrict__ avec){
    const int t    = threadIdx.x;
    const int lane = t & 31;
    const int g    = lane & 7;     // 8 lanes per row, lane g covers cols [g*8, g*8+8)
    float pc[8], qc[8], ac[8];
    #pragma unroll
    for (int i = 0; i < 8; i++){
        pc[i] = g_p[g*8+i];  qc[i] = g_q[g*8+i];  ac[i] = avec[g*8+i];
    }
    const int warp = (blockIdx.x*blockDim.x + t) >> 5;
    const int nw   = (gridDim.x*blockDim.x) >> 5;
    float zs = 0.f, zq = 0.f;
    for (int base = warp*8; base < MROWS; base += nw*8){
        #pragma unroll
        for (int h = 0; h < 2; h++){
            int row = base + h*4 + (lane >> 3);
            const uint2 pk0 = *reinterpret_cast<const uint2*>(&g_yh[(size_t)row*32 + g*4]);
            const uint2 pk1 = *reinterpret_cast<const uint2*>(&g_yh[(size_t)row*32 + g*4 + 2]);
            float2 f0 = __half22float2(*reinterpret_cast<const __half2*>(&pk0.x));
            float2 f1 = __half22float2(*reinterpret_cast<const __half2*>(&pk0.y));
            float2 f2 = __half22float2(*reinterpret_cast<const __half2*>(&pk1.x));
            float2 f3 = __half22float2(*reinterpret_cast<const __half2*>(&pk1.y));
            float z = 0.f;
            z += leakyf(f0.x*pc[0]+qc[0])*ac[0];
            z += leakyf(f0.y*pc[1]+qc[1])*ac[1];
            z += leakyf(f1.x*pc[2]+qc[2])*ac[2];
            z += leakyf(f1.y*pc[3]+qc[3])*ac[3];
            z += leakyf(f2.x*pc[4]+qc[4])*ac[4];
            z += leakyf(f2.y*pc[5]+qc[5])*ac[5];
            z += leakyf(f3.x*pc[6]+qc[6])*ac[6];
            z += leakyf(f3.y*pc[7]+qc[7])*ac[7];
            z += __shfl_xor_sync(0xffffffffu, z, 1);
            z += __shfl_xor_sync(0xffffffffu, z, 2);
            z += __shfl_xor_sync(0xffffffffu, z, 4);
            if (g == 0){
                g_zbuf[row] = z;
                zs += z; zq += z*z;
            }
        }
    }
    #pragma unroll
    for (int o = 16; o > 0; o >>= 1){
        zs += __shfl_xor_sync(0xffffffffu, zs, o);
        zq += __shfl_xor_sync(0xffffffffu, zq, o);
    }
    if (lane == 0){
        atomicAdd(&g_S3[0], zs);
        atomicAdd(&g_S3[1], zq);
    }
}

// ---------------- K6 ----------------
__global__ void k_fold3(const float* __restrict__ gamma3, const float* __restrict__ beta3){
    float mu  = g_S3[0] * (1.f/(float)MROWS);
    float var = g_S3[1] * (1.f/(float)MROWS) - mu*mu;
    float sc  = gamma3[0] * rsqrtf(var + EPSV);
    g_s3b3[0] = sc;
    g_s3b3[1] = beta3[0] - mu*sc;
}

// ---------------- K7: masked row softmax ----------------
__global__ __launch_bounds__(256) void k_softmax(const float* __restrict__ adj_mean,
                                                 float* __restrict__ out){
    const int row = blockIdx.x;
    const int t   = threadIdx.x;
    const int lane = t & 31, wid = t >> 5;
    const float s3 = g_s3b3[0], b3 = g_s3b3[1];

    const float4 zv = *reinterpret_cast<const float4*>(&g_zbuf[(size_t)row*NROWS + t*4]);
    const float4 mv = *reinterpret_cast<const float4*>(&adj_mean[(size_t)row*NROWS + t*4]);
    float v[4];
    {
        float zz[4] = {zv.x, zv.y, zv.z, zv.w};
        float mm[4] = {mv.x, mv.y, mv.z, mv.w};
        #pragma unroll
        for (int i = 0; i < 4; i++){
            float e = leakyf(zz[i]*s3 + b3);
            v[i] = (mm[i] > 0.f) ? e : NEGV;
        }
    }
    __shared__ float sred[8];
    float mx = fmaxf(fmaxf(v[0],v[1]), fmaxf(v[2],v[3]));
    #pragma unroll
    for (int o = 16; o > 0; o >>= 1) mx = fmaxf(mx, __shfl_xor_sync(0xffffffffu, mx, o));
    if (lane == 0) sred[wid] = mx;
    __syncthreads();
    if (t < 32){
        float m2 = (t < 8) ? sred[t] : -3.4e38f;
        #pragma unroll
        for (int o = 4; o > 0; o >>= 1) m2 = fmaxf(m2, __shfl_xor_sync(0xffffffffu, m2, o));
        if (t == 0) sred[0] = m2;
    }
    __syncthreads();
    mx = sred[0];
    __syncthreads();
    float e[4];
    #pragma unroll
    for (int i = 0; i < 4; i++) e[i] = __expf(v[i] - mx);
    float se = e[0]+e[1]+e[2]+e[3];
    #pragma unroll
    for (int o = 16; o > 0; o >>= 1) se += __shfl_xor_sync(0xffffffffu, se, o);
    if (lane == 0) sred[wid] = se;
    __syncthreads();
    if (t < 32){
        float s2 = (t < 8) ? sred[t] : 0.f;
        #pragma unroll
        for (int o = 4; o > 0; o >>= 1) s2 += __shfl_xor_sync(0xffffffffu, s2, o);
        if (t == 0) sred[0] = s2;
    }
    __syncthreads();
    const float inv = 1.f / sred[0];
    float4 ov = make_float4(e[0]*inv, e[1]*inv, e[2]*inv, e[3]*inv);
    *reinterpret_cast<float4*>(&out[(size_t)row*NROWS + t*4]) = ov;
}

// ---------------- launch ----------------
extern "C" void kernel_launch(void* const* d_in, const int* in_sizes, int n_in,
                              void* d_out, int out_size){
    const float* adj      = (const float*)d_in[0];
    const float* adj_mean = (const float*)d_in[1];
    const float* W        = (const float*)d_in[2];
    const float* a        = (const float*)d_in[3];
    const float* gamma1   = (const float*)d_in[4];
    const float* beta1    = (const float*)d_in[5];
    const float* gamma2   = (const float*)d_in[6];
    const float* beta2    = (const float*)d_in[7];
    const float* gamma3   = (const float*)d_in[8];
    const float* beta3    = (const float*)d_in[9];
    float* out = (float*)d_out;

    cudaFuncSetAttribute(k_gemm, cudaFuncAttributeMaxDynamicSharedMemorySize, SMEM_TOT);

    k_zero    <<<1, 128>>>();
    k_colstats<<<4096, 256>>>(adj);
    k_fold1   <<<1, 256>>>(W, gamma1, beta1);
    k_gemm    <<<MROWS/256, 256, SMEM_TOT>>>();
    k_fold2   <<<1, 64>>>(gamma2, beta2);
    k_zpass   <<<2048, 256>>>(a);
    k_fold3   <<<1, 1>>>(gamma3, beta3);
    k_softmax <<<NROWS, 256>>>(adj_mean, out);
}

// round 15
// speedup vs baseline: 1.3690x; 1.0443x over previous
#include <cuda_runtime.h>
#include <cuda_fp16.h>
#include <cstdint>
#include <cstddef>

#define NROWS   1024
#define MROWS   (NROWS*NROWS)
#define FIN     128
#define FHID    64
#define EPSV    1e-5f
#define ALPHAV  0.2f
#define NEGV    -9e15f

#define BSTRIDE 136   // B k-stride in fp16 (272B rows)
#define ASTR2   40    // A k-stride in fp16 (80B rows), K=32 phase tile

// ---------------- device scratch ----------------
__device__ __align__(16) float g_S1[FIN];
__device__ __align__(16) float g_Q1[FIN];
__device__ __align__(16) float g_cvec[FHID];
__device__ __align__(16) float g_S2[FHID];
__device__ __align__(16) float g_Q2[FHID];
__device__ __align__(16) float g_p[FHID];
__device__ __align__(16) float g_q[FHID];
__device__ __align__(16) float g_S3[2];
__device__ __align__(16) float g_s3b3[2];
__device__ __align__(16) __half g_Bh[FHID*BSTRIDE];         // fp16 W1 [n][k] padded
__device__ __align__(16) uint4 g_Ah[(size_t)MROWS*16];      // 256MB fp16 plane [row][128]
__device__ __align__(16) __half2 g_yh[(size_t)MROWS*32];    // 128MB fp16 y, PERMUTED cols
__device__ __align__(16) float g_zbuf[MROWS];

// y column permutation: logical c = nt*8 + 2*tc + j  <->  physical p = tc*16 + nt*2 + j

__device__ __forceinline__ float leakyf(float x){ return x >= 0.f ? x : ALPHAV*x; }

__device__ __forceinline__ uint32_t smem_u32(const void* p){
    uint32_t a;
    asm("{ .reg .u64 t; cvta.to.shared.u64 t, %1; cvt.u32.u64 %0, t; }" : "=r"(a) : "l"(p));
    return a;
}
__device__ __forceinline__ void ldm_x4(uint32_t* r, uint32_t addr){
    asm volatile("ldmatrix.sync.aligned.m8n8.x4.shared.b16 {%0,%1,%2,%3}, [%4];"
                 : "=r"(r[0]), "=r"(r[1]), "=r"(r[2]), "=r"(r[3]) : "r"(addr));
}
__device__ __forceinline__ void mma_f16(float* c, const uint32_t* a, const uint32_t* b){
    asm volatile("mma.sync.aligned.m16n8k16.row.col.f32.f16.f16.f32 "
        "{%0,%1,%2,%3}, {%4,%5,%6,%7}, {%8,%9}, {%0,%1,%2,%3};"
        : "+f"(c[0]), "+f"(c[1]), "+f"(c[2]), "+f"(c[3])
        : "r"(a[0]), "r"(a[1]), "r"(a[2]), "r"(a[3]), "r"(b[0]), "r"(b[1]));
}

// ---------------- K0 ----------------
__global__ void k_zero(){
    int t = threadIdx.x;
    if (t < FIN){ g_S1[t]=0.f; g_Q1[t]=0.f; }
    if (t < FHID){ g_S2[t]=0.f; g_Q2[t]=0.f; }
    if (t < 2) g_S3[t]=0.f;
}

// ---------------- K1: col stats of adj + fused single-fp16 conversion ------------
__global__ __launch_bounds__(256) void k_colstats(const float* __restrict__ adj){
    const int lane = threadIdx.x & 31;
    const int warp = (blockIdx.x*blockDim.x + threadIdx.x) >> 5;
    const int nw   = (gridDim.x*blockDim.x) >> 5;
    uint2* planeH = reinterpret_cast<uint2*>(g_Ah);
    float s0=0.f,s1=0.f,s2=0.f,s3=0.f,q0=0.f,q1=0.f,q2=0.f,q3=0.f;
    for (int r = warp*8; r < MROWS; r += nw*8){
        float4 v[8];
        #pragma unroll
        for (int i = 0; i < 8; i++)
            v[i] = *reinterpret_cast<const float4*>(adj + (size_t)(r+i)*FIN + lane*4);
        #pragma unroll
        for (int i = 0; i < 8; i++){
            s0+=v[i].x; q0+=v[i].x*v[i].x;
            s1+=v[i].y; q1+=v[i].y*v[i].y;
            s2+=v[i].z; q2+=v[i].z*v[i].z;
            s3+=v[i].w; q3+=v[i].w*v[i].w;
            __half2 h01 = __floats2half2_rn(v[i].x, v[i].y);
            __half2 h23 = __floats2half2_rn(v[i].z, v[i].w);
            planeH[(size_t)(r+i)*32 + lane] =
                make_uint2(*reinterpret_cast<uint32_t*>(&h01), *reinterpret_cast<uint32_t*>(&h23));
        }
    }
    __shared__ float bs[FIN], bq[FIN];
    if (threadIdx.x < FIN){ bs[threadIdx.x]=0.f; bq[threadIdx.x]=0.f; }
    __syncthreads();
    atomicAdd(&bs[lane*4+0], s0); atomicAdd(&bs[lane*4+1], s1);
    atomicAdd(&bs[lane*4+2], s2); atomicAdd(&bs[lane*4+3], s3);
    atomicAdd(&bq[lane*4+0], q0); atomicAdd(&bq[lane*4+1], q1);
    atomicAdd(&bq[lane*4+2], q2); atomicAdd(&bq[lane*4+3], q3);
    __syncthreads();
    if (threadIdx.x < FIN){
        atomicAdd(&g_S1[threadIdx.x], bs[threadIdx.x]);
        atomicAdd(&g_Q1[threadIdx.x], bq[threadIdx.x]);
    }
}

// ---------------- K2: fold BN1 into W -> single fp16 image [n][k] ----------------
__global__ void k_fold1(const float* __restrict__ W,
                        const float* __restrict__ gamma1,
                        const float* __restrict__ beta1){
    __shared__ float s1s[FIN], b1s[FIN];
    int t = threadIdx.x;
    if (t < FIN){
        float mu  = g_S1[t] * (1.f/(float)MROWS);
        float var = g_Q1[t] * (1.f/(float)MROWS) - mu*mu;
        float sc  = gamma1[t] * rsqrtf(var + EPSV);
        s1s[t] = sc;
        b1s[t] = beta1[t] - mu*sc;
    }
    __syncthreads();
    for (int i = t; i < FIN*FHID; i += blockDim.x){
        int k = i >> 6, n = i & 63;
        float w1 = s1s[k] * W[i];
        g_Bh[n*BSTRIDE + k] = __float2half_rn(w1);
    }
    if (t < FHID){
        float acc = 0.f;
        for (int j = 0; j < FIN; j++) acc += b1s[j] * W[j*FHID + t];
        g_cvec[t] = acc;
    }
}

// ---------------- K3: fp16 GEMM, 256-row CTA, 2/SM, 3-buffer depth-2 pipeline ---
// dyn smem: AH0..AH2 (3 x 20480) + BH(17408) = 78848
#define SOFF_AH0 0
#define ABUF_SZ  20480
#define SOFF_BH  61440
#define SMEM_TOT 78848

__device__ __forceinline__ void stage_phase(uint32_t dstH, int row0, int t, int ph){
    #pragma unroll
    for (int i = 0; i < 4; i++){
        int idx = t + i*256;          // 0..1023
        int r = idx >> 2, c = idx & 3;
        size_t gidx = (size_t)(row0 + r)*16 + (size_t)(ph*4 + c);
        uint32_t so = (uint32_t)(r*(ASTR2*2) + c*16);
        asm volatile("cp.async.cg.shared.global [%0], [%1], 16;"
            :: "r"(dstH + so), "l"(g_Ah + gidx) : "memory");
    }
}

__global__ void __launch_bounds__(256, 2) k_gemm(){
    extern __shared__ __align__(1024) char smem[];
    const uint32_t sb = smem_u32(smem);
    const int t = threadIdx.x;
    const int w = t >> 5, lane = t & 31;
    const int g  = lane >> 2, tc = lane & 3;
    const int row0 = blockIdx.x * 256;

    __shared__ float cs[FHID], cq[FHID];
    if (t < FHID){ cs[t]=0.f; cq[t]=0.f; }

    // prologue: issue phase-0 and phase-1 copies (depth 2)
    stage_phase(sb + SOFF_AH0, row0, t, 0);
    asm volatile("cp.async.commit_group;" ::: "memory");
    stage_phase(sb + SOFF_AH0 + ABUF_SZ, row0, t, 1);
    asm volatile("cp.async.commit_group;" ::: "memory");

    // B: flat copy of prebuilt fp16 image (1088 uint4)
    {
        const uint4* sh = reinterpret_cast<const uint4*>(g_Bh);
        uint4* dh = reinterpret_cast<uint4*>(smem + SOFF_BH);
        #pragma unroll
        for (int i = 0; i < 5; i++){
            int idx = t + i*256;
            if (idx < 1088) dh[idx] = sh[idx];
        }
    }

    // fragment base offsets: warp w owns rows w*32..w*32+31 (2 m-tiles of 16)
    const uint32_t aOffBase =
        (uint32_t)((w*32 + (lane & 15))*(ASTR2*2) + (lane >> 4)*16);
    const uint32_t bBase = sb + SOFF_BH +
        (uint32_t)(((lane & 7) + ((lane & 16) >> 1))*BSTRIDE + (lane & 8))*2u;

    float acc[2][8][4];
    #pragma unroll
    for (int mt = 0; mt < 2; mt++)
        #pragma unroll
        for (int nt = 0; nt < 8; nt++)
            #pragma unroll
            for (int i = 0; i < 4; i++) acc[mt][nt][i] = 0.f;

    #pragma unroll
    for (int ph = 0; ph < 4; ph++){
        if (ph < 3){
            asm volatile("cp.async.wait_group 1;" ::: "memory");
        } else {
            asm volatile("cp.async.wait_group 0;" ::: "memory");
        }
        __syncthreads();
        if (ph < 2){
            stage_phase(sb + SOFF_AH0 + ((ph+2)%3)*ABUF_SZ, row0, t, ph+2);
            asm volatile("cp.async.commit_group;" ::: "memory");
        }
        const uint32_t aBase = sb + SOFF_AH0 + (ph%3)*ABUF_SZ + aOffBase;
        #pragma unroll
        for (int ksl = 0; ksl < 2; ksl++){
            const uint32_t kA = (uint32_t)(ksl*32);            // 16 fp16 = 32B
            const uint32_t kB = (uint32_t)((ph*2 + ksl)*32);
            uint32_t ah0[4], ah1[4];
            ldm_x4(ah0, aBase + kA);
            ldm_x4(ah1, aBase + kA + (uint32_t)(16*ASTR2*2));
            #pragma unroll
            for (int p = 0; p < 4; p++){
                const uint32_t bo = bBase + kB + (uint32_t)(p*16*BSTRIDE*2);
                uint32_t bh[4];
                ldm_x4(bh, bo);
                mma_f16(acc[0][2*p],   ah0, bh);
                mma_f16(acc[1][2*p],   ah1, bh);
                mma_f16(acc[0][2*p+1], ah0, bh+2);
                mma_f16(acc[1][2*p+1], ah1, bh+2);
            }
        }
    }

    // epilogue: permuted-layout y stores (2x STG.128 per row) + BN2 stats
    float sreg[8][2], qreg[8][2];
    #pragma unroll
    for (int nt = 0; nt < 8; nt++){ sreg[nt][0]=0.f; sreg[nt][1]=0.f; qreg[nt][0]=0.f; qreg[nt][1]=0.f; }

    #pragma unroll
    for (int mt = 0; mt < 2; mt++){
        const int r0 = row0 + w*32 + mt*16 + g;
        const int r1 = r0 + 8;
        uint32_t h0[8], h1[8];
        #pragma unroll
        for (int nt = 0; nt < 8; nt++){
            const int c0 = nt*8 + 2*tc;
            const float cv0 = __ldg(&g_cvec[c0]);
            const float cv1 = __ldg(&g_cvec[c0+1]);
            __half2 a0 = __floats2half2_rn(acc[mt][nt][0] + cv0, acc[mt][nt][1] + cv1);
            __half2 a1 = __floats2half2_rn(acc[mt][nt][2] + cv0, acc[mt][nt][3] + cv1);
            h0[nt] = *reinterpret_cast<uint32_t*>(&a0);
            h1[nt] = *reinterpret_cast<uint32_t*>(&a1);
            float2 f0 = __half22float2(a0);
            float2 f1 = __half22float2(a1);
            sreg[nt][0] += f0.x + f1.x;  qreg[nt][0] += f0.x*f0.x + f1.x*f1.x;
            sreg[nt][1] += f0.y + f1.y;  qreg[nt][1] += f0.y*f0.y + f1.y*f1.y;
        }
        // physical half2 index for this thread: tc*8 + nt  -> contiguous [tc*8, tc*8+8)
        uint4* d0 = reinterpret_cast<uint4*>(&g_yh[(size_t)r0*32 + tc*8]);
        uint4* d1 = reinterpret_cast<uint4*>(&g_yh[(size_t)r1*32 + tc*8]);
        d0[0] = make_uint4(h0[0], h0[1], h0[2], h0[3]);
        d0[1] = make_uint4(h0[4], h0[5], h0[6], h0[7]);
        d1[0] = make_uint4(h1[0], h1[1], h1[2], h1[3]);
        d1[1] = make_uint4(h1[4], h1[5], h1[6], h1[7]);
    }
    #pragma unroll
    for (int nt = 0; nt < 8; nt++){
        #pragma unroll
        for (int j = 0; j < 2; j++){
            float s = sreg[nt][j], q = qreg[nt][j];
            #pragma unroll
            for (int o = 4; o <= 16; o <<= 1){
                s += __shfl_xor_sync(0xffffffffu, s, o);
                q += __shfl_xor_sync(0xffffffffu, q, o);
            }
            if (lane < 4){
                atomicAdd(&cs[nt*8 + 2*tc + j], s);
                atomicAdd(&cq[nt*8 + 2*tc + j], q);
            }
        }
    }
    __syncthreads();
    if (t < FHID){
        atomicAdd(&g_S2[t], cs[t]);
        atomicAdd(&g_Q2[t], cq[t]);
    }
}

// ---------------- K4 ----------------
__global__ void k_fold2(const float* __restrict__ gamma2, const float* __restrict__ beta2){
    int t = threadIdx.x;
    if (t < FHID){
        float mu  = g_S2[t] * (1.f/(float)MROWS);
        float var = g_Q2[t] * (1.f/(float)MROWS) - mu*mu;
        float sc  = gamma2[t] * rsqrtf(var + EPSV);
        g_p[t] = sc;
        g_q[t] = beta2[t] - mu*sc;
    }
}

// ---------------- K5: z pass (fp16 y, permuted layout) ----------------
__global__ __launch_bounds__(256) void k_zpass(const float* __restrict__ avec){
    const int t    = threadIdx.x;
    const int lane = t & 31;
    const int g    = lane & 7;     // lane g covers physical half2 indices [g*4, g*4+4)
    float pc[8], qc[8], ac[8];
    #pragma unroll
    for (int i = 0; i < 4; i++){
        int h  = g*4 + i;              // physical half2 index
        int tc = h >> 3, nt = h & 7;
        int c  = nt*8 + 2*tc;          // logical column of the pair
        pc[2*i]   = g_p[c];    qc[2*i]   = g_q[c];    ac[2*i]   = avec[c];
        pc[2*i+1] = g_p[c+1];  qc[2*i+1] = g_q[c+1];  ac[2*i+1] = avec[c+1];
    }
    const int warp = (blockIdx.x*blockDim.x + t) >> 5;
    const int nw   = (gridDim.x*blockDim.x) >> 5;
    float zs = 0.f, zq = 0.f;
    for (int base = warp*8; base < MROWS; base += nw*8){
        #pragma unroll
        for (int h = 0; h < 2; h++){
            int row = base + h*4 + (lane >> 3);
            const uint4 pk = *reinterpret_cast<const uint4*>(&g_yh[(size_t)row*32 + g*4]);
            float2 f0 = __half22float2(*reinterpret_cast<const __half2*>(&pk.x));
            float2 f1 = __half22float2(*reinterpret_cast<const __half2*>(&pk.y));
            float2 f2 = __half22float2(*reinterpret_cast<const __half2*>(&pk.z));
            float2 f3 = __half22float2(*reinterpret_cast<const __half2*>(&pk.w));
            float z = 0.f;
            z += leakyf(f0.x*pc[0]+qc[0])*ac[0];
            z += leakyf(f0.y*pc[1]+qc[1])*ac[1];
            z += leakyf(f1.x*pc[2]+qc[2])*ac[2];
            z += leakyf(f1.y*pc[3]+qc[3])*ac[3];
            z += leakyf(f2.x*pc[4]+qc[4])*ac[4];
            z += leakyf(f2.y*pc[5]+qc[5])*ac[5];
            z += leakyf(f3.x*pc[6]+qc[6])*ac[6];
            z += leakyf(f3.y*pc[7]+qc[7])*ac[7];
            z += __shfl_xor_sync(0xffffffffu, z, 1);
            z += __shfl_xor_sync(0xffffffffu, z, 2);
            z += __shfl_xor_sync(0xffffffffu, z, 4);
            if (g == 0){
                g_zbuf[row] = z;
                zs += z; zq += z*z;
            }
        }
    }
    #pragma unroll
    for (int o = 16; o > 0; o >>= 1){
        zs += __shfl_xor_sync(0xffffffffu, zs, o);
        zq += __shfl_xor_sync(0xffffffffu, zq, o);
    }
    if (lane == 0){
        atomicAdd(&g_S3[0], zs);
        atomicAdd(&g_S3[1], zq);
    }
}

// ---------------- K6 ----------------
__global__ void k_fold3(const float* __restrict__ gamma3, const float* __restrict__ beta3){
    float mu  = g_S3[0] * (1.f/(float)MROWS);
    float var = g_S3[1] * (1.f/(float)MROWS) - mu*mu;
    float sc  = gamma3[0] * rsqrtf(var + EPSV);
    g_s3b3[0] = sc;
    g_s3b3[1] = beta3[0] - mu*sc;
}

// ---------------- K7: masked row softmax ----------------
__global__ __launch_bounds__(256) void k_softmax(const float* __restrict__ adj_mean,
                                                 float* __restrict__ out){
    const int row = blockIdx.x;
    const int t   = threadIdx.x;
    const int lane = t & 31, wid = t >> 5;
    const float s3 = g_s3b3[0], b3 = g_s3b3[1];

    const float4 zv = *reinterpret_cast<const float4*>(&g_zbuf[(size_t)row*NROWS + t*4]);
    const float4 mv = *reinterpret_cast<const float4*>(&adj_mean[(size_t)row*NROWS + t*4]);
    float v[4];
    {
        float zz[4] = {zv.x, zv.y, zv.z, zv.w};
        float mm[4] = {mv.x, mv.y, mv.z, mv.w};
        #pragma unroll
        for (int i = 0; i < 4; i++){
            float e = leakyf(zz[i]*s3 + b3);
            v[i] = (mm[i] > 0.f) ? e : NEGV;
        }
    }
    __shared__ float sred[8];
    float mx = fmaxf(fmaxf(v[0],v[1]), fmaxf(v[2],v[3]));
    #pragma unroll
    for (int o = 16; o > 0; o >>= 1) mx = fmaxf(mx, __shfl_xor_sync(0xffffffffu, mx, o));
    if (lane == 0) sred[wid] = mx;
    __syncthreads();
    if (t < 32){
        float m2 = (t < 8) ? sred[t] : -3.4e38f;
        #pragma unroll
        for (int o = 4; o > 0; o >>= 1) m2 = fmaxf(m2, __shfl_xor_sync(0xffffffffu, m2, o));
        if (t == 0) sred[0] = m2;
    }
    __syncthreads();
    mx = sred[0];
    __syncthreads();
    float e[4];
    #pragma unroll
    for (int i = 0; i < 4; i++) e[i] = __expf(v[i] - mx);
    float se = e[0]+e[1]+e[2]+e[3];
    #pragma unroll
    for (int o = 16; o > 0; o >>= 1) se += __shfl_xor_sync(0xffffffffu, se, o);
    if (lane == 0) sred[wid] = se;
    __syncthreads();
    if (t < 32){
        float s2 = (t < 8) ? sred[t] : 0.f;
        #pragma unroll
        for (int o = 4; o > 0; o >>= 1) s2 += __shfl_xor_sync(0xffffffffu, s2, o);
        if (t == 0) sred[0] = s2;
    }
    __syncthreads();
    const float inv = 1.f / sred[0];
    float4 ov = make_float4(e[0]*inv, e[1]*inv, e[2]*inv, e[3]*inv);
    *reinterpret_cast<float4*>(&out[(size_t)row*NROWS + t*4]) = ov;
}

// ---------------- launch ----------------
extern "C" void kernel_launch(void* const* d_in, const int* in_sizes, int n_in,
                              void* d_out, int out_size){
    const float* adj      = (const float*)d_in[0];
    const float* adj_mean = (const float*)d_in[1];
    const float* W        = (const float*)d_in[2];
    const float* a        = (const float*)d_in[3];
    const float* gamma1   = (const float*)d_in[4];
    const float* beta1    = (const float*)d_in[5];
    const float* gamma2   = (const float*)d_in[6];
    const float* beta2    = (const float*)d_in[7];
    const float* gamma3   = (const float*)d_in[8];
    const float* beta3    = (const float*)d_in[9];
    float* out = (float*)d_out;

    cudaFuncSetAttribute(k_gemm, cudaFuncAttributeMaxDynamicSharedMemorySize, SMEM_TOT);

    k_zero    <<<1, 128>>>();
    k_colstats<<<4096, 256>>>(adj);
    k_fold1   <<<1, 256>>>(W, gamma1, beta1);
    k_gemm    <<<MROWS/256, 256, SMEM_TOT>>>();
    k_fold2   <<<1, 64>>>(gamma2, beta2);
    k_zpass   <<<2048, 256>>>(a);
    k_fold3   <<<1, 1>>>(gamma3, beta3);
    k_softmax <<<NROWS, 256>>>(adj_mean, out);
}

// round 17
// speedup vs baseline: 1.4056x; 1.0267x over previous
#include <cuda_runtime.h>
#include <cuda_fp16.h>
#include <cstdint>
#include <cstddef>

#define NROWS   1024
#define MROWS   (NROWS*NROWS)
#define FIN     128
#define FHID    64
#define EPSV    1e-5f
#define ALPHAV  0.2f
#define NEGV    -9e15f

#define BSTRIDE 136   // B k-stride in fp16 (272B rows)
#define ASTR2   40    // A k-stride in fp16 (80B rows), K=32 phase tile

// ---------------- device scratch ----------------
__device__ __align__(16) float g_S1[FIN];
__device__ __align__(16) float g_Q1[FIN];
__device__ __align__(16) float g_cvec[FHID];
__device__ __align__(16) float g_S2[FHID];
__device__ __align__(16) float g_Q2[FHID];
__device__ __align__(16) float g_p[FHID];
__device__ __align__(16) float g_q[FHID];
__device__ __align__(16) float g_S3[2];
__device__ __align__(16) float g_s3b3[2];
__device__ __align__(16) __half g_Bh[FHID*BSTRIDE];         // fp16 W1 [n][k] padded
__device__ __align__(16) uint4 g_Ah[(size_t)MROWS*16];      // 256MB fp16 plane [row][128]
__device__ __align__(16) __half2 g_yh[(size_t)MROWS*32];    // 128MB fp16 y, PERMUTED cols
__device__ __align__(16) float g_zbuf[MROWS];

// y column permutation: logical c = nt*8 + 2*tc + j  <->  physical p = tc*16 + nt*2 + j

__device__ __forceinline__ float leakyf(float x){ return x >= 0.f ? x : ALPHAV*x; }

__device__ __forceinline__ uint32_t smem_u32(const void* p){
    uint32_t a;
    asm("{ .reg .u64 t; cvta.to.shared.u64 t, %1; cvt.u32.u64 %0, t; }" : "=r"(a) : "l"(p));
    return a;
}
__device__ __forceinline__ void ldm_x4(uint32_t* r, uint32_t addr){
    asm volatile("ldmatrix.sync.aligned.m8n8.x4.shared.b16 {%0,%1,%2,%3}, [%4];"
                 : "=r"(r[0]), "=r"(r[1]), "=r"(r[2]), "=r"(r[3]) : "r"(addr));
}
__device__ __forceinline__ void mma_f16(float* c, const uint32_t* a, const uint32_t* b){
    asm volatile("mma.sync.aligned.m16n8k16.row.col.f32.f16.f16.f32 "
        "{%0,%1,%2,%3}, {%4,%5,%6,%7}, {%8,%9}, {%0,%1,%2,%3};"
        : "+f"(c[0]), "+f"(c[1]), "+f"(c[2]), "+f"(c[3])
        : "r"(a[0]), "r"(a[1]), "r"(a[2]), "r"(a[3]), "r"(b[0]), "r"(b[1]));
}

// ---------------- K0 ----------------
__global__ void k_zero(){
    int t = threadIdx.x;
    if (t < FIN){ g_S1[t]=0.f; g_Q1[t]=0.f; }
    if (t < FHID){ g_S2[t]=0.f; g_Q2[t]=0.f; }
    if (t < 2) g_S3[t]=0.f;
}

// ---------------- K1: col stats of adj + fused single-fp16 conversion ------------
__global__ __launch_bounds__(256) void k_colstats(const float* __restrict__ adj){
    const int lane = threadIdx.x & 31;
    const int warp = (blockIdx.x*blockDim.x + threadIdx.x) >> 5;
    const int nw   = (gridDim.x*blockDim.x) >> 5;
    uint2* planeH = reinterpret_cast<uint2*>(g_Ah);
    float s0=0.f,s1=0.f,s2=0.f,s3=0.f,q0=0.f,q1=0.f,q2=0.f,q3=0.f;
    for (int r = warp*8; r < MROWS; r += nw*8){
        float4 v[8];
        #pragma unroll
        for (int i = 0; i < 8; i++)
            v[i] = *reinterpret_cast<const float4*>(adj + (size_t)(r+i)*FIN + lane*4);
        #pragma unroll
        for (int i = 0; i < 8; i++){
            s0+=v[i].x; q0+=v[i].x*v[i].x;
            s1+=v[i].y; q1+=v[i].y*v[i].y;
            s2+=v[i].z; q2+=v[i].z*v[i].z;
            s3+=v[i].w; q3+=v[i].w*v[i].w;
            __half2 h01 = __floats2half2_rn(v[i].x, v[i].y);
            __half2 h23 = __floats2half2_rn(v[i].z, v[i].w);
            planeH[(size_t)(r+i)*32 + lane] =
                make_uint2(*reinterpret_cast<uint32_t*>(&h01), *reinterpret_cast<uint32_t*>(&h23));
        }
    }
    __shared__ float bs[FIN], bq[FIN];
    if (threadIdx.x < FIN){ bs[threadIdx.x]=0.f; bq[threadIdx.x]=0.f; }
    __syncthreads();
    atomicAdd(&bs[lane*4+0], s0); atomicAdd(&bs[lane*4+1], s1);
    atomicAdd(&bs[lane*4+2], s2); atomicAdd(&bs[lane*4+3], s3);
    atomicAdd(&bq[lane*4+0], q0); atomicAdd(&bq[lane*4+1], q1);
    atomicAdd(&bq[lane*4+2], q2); atomicAdd(&bq[lane*4+3], q3);
    __syncthreads();
    if (threadIdx.x < FIN){
        atomicAdd(&g_S1[threadIdx.x], bs[threadIdx.x]);
        atomicAdd(&g_Q1[threadIdx.x], bq[threadIdx.x]);
    }
}

// ---------------- K2: fold BN1 into W -> single fp16 image [n][k] ----------------
__global__ void k_fold1(const float* __restrict__ W,
                        const float* __restrict__ gamma1,
                        const float* __restrict__ beta1){
    __shared__ float s1s[FIN], b1s[FIN];
    int t = threadIdx.x;
    if (t < FIN){
        float mu  = g_S1[t] * (1.f/(float)MROWS);
        float var = g_Q1[t] * (1.f/(float)MROWS) - mu*mu;
        float sc  = gamma1[t] * rsqrtf(var + EPSV);
        s1s[t] = sc;
        b1s[t] = beta1[t] - mu*sc;
    }
    __syncthreads();
    for (int i = t; i < FIN*FHID; i += blockDim.x){
        int k = i >> 6, n = i & 63;
        float w1 = s1s[k] * W[i];
        g_Bh[n*BSTRIDE + k] = __float2half_rn(w1);
    }
    if (t < FHID){
        float acc = 0.f;
        for (int j = 0; j < FIN; j++) acc += b1s[j] * W[j*FHID + t];
        g_cvec[t] = acc;
    }
}

// ---------------- K3: fp16 GEMM, 128-row CTA, 4/SM, 3-buffer depth-2 pipeline ---
// dyn smem: AH0..AH2 (3 x 10240) + BH(17408) = 48128
#define SOFF_AH0 0
#define ABUF_SZ  10240
#define SOFF_BH  30720
#define SMEM_TOT 48128

__device__ __forceinline__ void stage_phase(uint32_t dstH, int row0, int t, int ph){
    #pragma unroll
    for (int i = 0; i < 4; i++){
        int idx = t + i*128;          // 0..511
        int r = idx >> 2, c = idx & 3;
        size_t gidx = (size_t)(row0 + r)*16 + (size_t)(ph*4 + c);
        uint32_t so = (uint32_t)(r*(ASTR2*2) + c*16);
        asm volatile("cp.async.cg.shared.global [%0], [%1], 16;"
            :: "r"(dstH + so), "l"(g_Ah + gidx) : "memory");
    }
}

__global__ void __launch_bounds__(128, 4) k_gemm(){
    extern __shared__ __align__(1024) char smem[];
    const uint32_t sb = smem_u32(smem);
    const int t = threadIdx.x;
    const int w = t >> 5, lane = t & 31;
    const int g  = lane >> 2, tc = lane & 3;
    const int row0 = blockIdx.x * 128;

    __shared__ float cs[FHID], cq[FHID];
    if (t < FHID){ cs[t]=0.f; cq[t]=0.f; }

    // prologue: issue phase-0 and phase-1 copies (depth 2)
    stage_phase(sb + SOFF_AH0, row0, t, 0);
    asm volatile("cp.async.commit_group;" ::: "memory");
    stage_phase(sb + SOFF_AH0 + ABUF_SZ, row0, t, 1);
    asm volatile("cp.async.commit_group;" ::: "memory");

    // B: flat copy of prebuilt fp16 image (1088 uint4)
    {
        const uint4* sh = reinterpret_cast<const uint4*>(g_Bh);
        uint4* dh = reinterpret_cast<uint4*>(smem + SOFF_BH);
        #pragma unroll
        for (int i = 0; i < 9; i++){
            int idx = t + i*128;
            if (idx < 1088) dh[idx] = sh[idx];
        }
    }

    // fragment base offsets: warp w owns rows w*32..w*32+31 (2 m-tiles of 16)
    const uint32_t aOffBase =
        (uint32_t)((w*32 + (lane & 15))*(ASTR2*2) + (lane >> 4)*16);
    const uint32_t bBase = sb + SOFF_BH +
        (uint32_t)(((lane & 7) + ((lane & 16) >> 1))*BSTRIDE + (lane & 8))*2u;

    float acc[2][8][4];
    #pragma unroll
    for (int mt = 0; mt < 2; mt++)
        #pragma unroll
        for (int nt = 0; nt < 8; nt++)
            #pragma unroll
            for (int i = 0; i < 4; i++) acc[mt][nt][i] = 0.f;

    #pragma unroll
    for (int ph = 0; ph < 4; ph++){
        if (ph < 3){
            asm volatile("cp.async.wait_group 1;" ::: "memory");
        } else {
            asm volatile("cp.async.wait_group 0;" ::: "memory");
        }
        __syncthreads();
        if (ph < 2){
            stage_phase(sb + SOFF_AH0 + ((ph+2)%3)*ABUF_SZ, row0, t, ph+2);
            asm volatile("cp.async.commit_group;" ::: "memory");
        }
        const uint32_t aBase = sb + SOFF_AH0 + (ph%3)*ABUF_SZ + aOffBase;
        #pragma unroll
        for (int ksl = 0; ksl < 2; ksl++){
            const uint32_t kA = (uint32_t)(ksl*32);            // 16 fp16 = 32B
            const uint32_t kB = (uint32_t)((ph*2 + ksl)*32);
            uint32_t ah0[4], ah1[4];
            ldm_x4(ah0, aBase + kA);
            ldm_x4(ah1, aBase + kA + (uint32_t)(16*ASTR2*2));
            #pragma unroll
            for (int p = 0; p < 4; p++){
                const uint32_t bo = bBase + kB + (uint32_t)(p*16*BSTRIDE*2);
                uint32_t bh[4];
                ldm_x4(bh, bo);
                mma_f16(acc[0][2*p],   ah0, bh);
                mma_f16(acc[1][2*p],   ah1, bh);
                mma_f16(acc[0][2*p+1], ah0, bh+2);
                mma_f16(acc[1][2*p+1], ah1, bh+2);
            }
        }
    }

    // epilogue: permuted-layout y stores (2x STG.128 per row) + BN2 stats
    float sreg[8][2], qreg[8][2];
    #pragma unroll
    for (int nt = 0; nt < 8; nt++){ sreg[nt][0]=0.f; sreg[nt][1]=0.f; qreg[nt][0]=0.f; qreg[nt][1]=0.f; }

    #pragma unroll
    for (int mt = 0; mt < 2; mt++){
        const int r0 = row0 + w*32 + mt*16 + g;
        const int r1 = r0 + 8;
        uint32_t h0[8], h1[8];
        #pragma unroll
        for (int nt = 0; nt < 8; nt++){
            const int c0 = nt*8 + 2*tc;
            const float cv0 = __ldg(&g_cvec[c0]);
            const float cv1 = __ldg(&g_cvec[c0+1]);
            __half2 a0 = __floats2half2_rn(acc[mt][nt][0] + cv0, acc[mt][nt][1] + cv1);
            __half2 a1 = __floats2half2_rn(acc[mt][nt][2] + cv0, acc[mt][nt][3] + cv1);
            h0[nt] = *reinterpret_cast<uint32_t*>(&a0);
            h1[nt] = *reinterpret_cast<uint32_t*>(&a1);
            float2 f0 = __half22float2(a0);
            float2 f1 = __half22float2(a1);
            sreg[nt][0] += f0.x + f1.x;  qreg[nt][0] += f0.x*f0.x + f1.x*f1.x;
            sreg[nt][1] += f0.y + f1.y;  qreg[nt][1] += f0.y*f0.y + f1.y*f1.y;
        }
        // physical half2 index for this thread: tc*8 + nt  -> contiguous [tc*8, tc*8+8)
        uint4* d0 = reinterpret_cast<uint4*>(&g_yh[(size_t)r0*32 + tc*8]);
        uint4* d1 = reinterpret_cast<uint4*>(&g_yh[(size_t)r1*32 + tc*8]);
        d0[0] = make_uint4(h0[0], h0[1], h0[2], h0[3]);
        d0[1] = make_uint4(h0[4], h0[5], h0[6], h0[7]);
        d1[0] = make_uint4(h1[0], h1[1], h1[2], h1[3]);
        d1[1] = make_uint4(h1[4], h1[5], h1[6], h1[7]);
    }
    #pragma unroll
    for (int nt = 0; nt < 8; nt++){
        #pragma unroll
        for (int j = 0; j < 2; j++){
            float s = sreg[nt][j], q = qreg[nt][j];
            #pragma unroll
            for (int o = 4; o <= 16; o <<= 1){
                s += __shfl_xor_sync(0xffffffffu, s, o);
                q += __shfl_xor_sync(0xffffffffu, q, o);
            }
            if (lane < 4){
                atomicAdd(&cs[nt*8 + 2*tc + j], s);
                atomicAdd(&cq[nt*8 + 2*tc + j], q);
            }
        }
    }
    __syncthreads();
    if (t < FHID){
        atomicAdd(&g_S2[t], cs[t]);
        atomicAdd(&g_Q2[t], cq[t]);
    }
}

// ---------------- K4 ----------------
__global__ void k_fold2(const float* __restrict__ gamma2, const float* __restrict__ beta2){
    int t = threadIdx.x;
    if (t < FHID){
        float mu  = g_S2[t] * (1.f/(float)MROWS);
        float var = g_Q2[t] * (1.f/(float)MROWS) - mu*mu;
        float sc  = gamma2[t] * rsqrtf(var + EPSV);
        g_p[t] = sc;
        g_q[t] = beta2[t] - mu*sc;
    }
}

// ---------------- K5: z pass (fp16 y, permuted layout) ----------------
__global__ __launch_bounds__(256) void k_zpass(const float* __restrict__ avec){
    const int t    = threadIdx.x;
    const int lane = t & 31;
    const int g    = lane & 7;     // lane g covers physical half2 indices [g*4, g*4+4)
    float pc[8], qc[8], ac[8];
    #pragma unroll
    for (int i = 0; i < 4; i++){
        int h  = g*4 + i;              // physical half2 index
        int tc = h >> 3, nt = h & 7;
        int c  = nt*8 + 2*tc;          // logical column of the pair
        pc[2*i]   = g_p[c];    qc[2*i]   = g_q[c];    ac[2*i]   = avec[c];
        pc[2*i+1] = g_p[c+1];  qc[2*i+1] = g_q[c+1];  ac[2*i+1] = avec[c+1];
    }
    const int warp = (blockIdx.x*blockDim.x + t) >> 5;
    const int nw   = (gridDim.x*blockDim.x) >> 5;
    float zs = 0.f, zq = 0.f;
    for (int base = warp*8; base < MROWS; base += nw*8){
        #pragma unroll
        for (int h = 0; h < 2; h++){
            int row = base + h*4 + (lane >> 3);
            const uint4 pk = *reinterpret_cast<const uint4*>(&g_yh[(size_t)row*32 + g*4]);
            float2 f0 = __half22float2(*reinterpret_cast<const __half2*>(&pk.x));
            float2 f1 = __half22float2(*reinterpret_cast<const __half2*>(&pk.y));
            float2 f2 = __half22float2(*reinterpret_cast<const __half2*>(&pk.z));
            float2 f3 = __half22float2(*reinterpret_cast<const __half2*>(&pk.w));
            float z = 0.f;
            z += leakyf(f0.x*pc[0]+qc[0])*ac[0];
            z += leakyf(f0.y*pc[1]+qc[1])*ac[1];
            z += leakyf(f1.x*pc[2]+qc[2])*ac[2];
            z += leakyf(f1.y*pc[3]+qc[3])*ac[3];
            z += leakyf(f2.x*pc[4]+qc[4])*ac[4];
            z += leakyf(f2.y*pc[5]+qc[5])*ac[5];
            z += leakyf(f3.x*pc[6]+qc[6])*ac[6];
            z += leakyf(f3.y*pc[7]+qc[7])*ac[7];
            z += __shfl_xor_sync(0xffffffffu, z, 1);
            z += __shfl_xor_sync(0xffffffffu, z, 2);
            z += __shfl_xor_sync(0xffffffffu, z, 4);
            if (g == 0){
                g_zbuf[row] = z;
                zs += z; zq += z*z;
            }
        }
    }
    #pragma unroll
    for (int o = 16; o > 0; o >>= 1){
        zs += __shfl_xor_sync(0xffffffffu, zs, o);
        zq += __shfl_xor_sync(0xffffffffu, zq, o);
    }
    if (lane == 0){
        atomicAdd(&g_S3[0], zs);
        atomicAdd(&g_S3[1], zq);
    }
}

// ---------------- K6 ----------------
__global__ void k_fold3(const float* __restrict__ gamma3, const float* __restrict__ beta3){
    float mu  = g_S3[0] * (1.f/(float)MROWS);
    float var = g_S3[1] * (1.f/(float)MROWS) - mu*mu;
    float sc  = gamma3[0] * rsqrtf(var + EPSV);
    g_s3b3[0] = sc;
    g_s3b3[1] = beta3[0] - mu*sc;
}

// ---------------- K7: masked row softmax ----------------
__global__ __launch_bounds__(256) void k_softmax(const float* __restrict__ adj_mean,
                                                 float* __restrict__ out){
    const int row = blockIdx.x;
    const int t   = threadIdx.x;
    const int lane = t & 31, wid = t >> 5;
    const float s3 = g_s3b3[0], b3 = g_s3b3[1];

    const float4 zv = *reinterpret_cast<const float4*>(&g_zbuf[(size_t)row*NROWS + t*4]);
    const float4 mv = *reinterpret_cast<const float4*>(&adj_mean[(size_t)row*NROWS + t*4]);
    float v[4];
    {
        float zz[4] = {zv.x, zv.y, zv.z, zv.w};
        float mm[4] = {mv.x, mv.y, mv.z, mv.w};
        #pragma unroll
        for (int i = 0; i < 4; i++){
            float e = leakyf(zz[i]*s3 + b3);
            v[i] = (mm[i] > 0.f) ? e : NEGV;
        }
    }
    __shared__ float sred[8];
    float mx = fmaxf(fmaxf(v[0],v[1]), fmaxf(v[2],v[3]));
    #pragma unroll
    for (int o = 16; o > 0; o >>= 1) mx = fmaxf(mx, __shfl_xor_sync(0xffffffffu, mx, o));
    if (lane == 0) sred[wid] = mx;
    __syncthreads();
    if (t < 32){
        float m2 = (t < 8) ? sred[t] : -3.4e38f;
        #pragma unroll
        for (int o = 4; o > 0; o >>= 1) m2 = fmaxf(m2, __shfl_xor_sync(0xffffffffu, m2, o));
        if (t == 0) sred[0] = m2;
    }
    __syncthreads();
    mx = sred[0];
    __syncthreads();
    float e[4];
    #pragma unroll
    for (int i = 0; i < 4; i++) e[i] = __expf(v[i] - mx);
    float se = e[0]+e[1]+e[2]+e[3];
    #pragma unroll
    for (int o = 16; o > 0; o >>= 1) se += __shfl_xor_sync(0xffffffffu, se, o);
    if (lane == 0) sred[wid] = se;
    __syncthreads();
    if (t < 32){
        float s2 = (t < 8) ? sred[t] : 0.f;
        #pragma unroll
        for (int o = 4; o > 0; o >>= 1) s2 += __shfl_xor_sync(0xffffffffu, s2, o);
        if (t == 0) sred[0] = s2;
    }
    __syncthreads();
    const float inv = 1.f / sred[0];
    float4 ov = make_float4(e[0]*inv, e[1]*inv, e[2]*inv, e[3]*inv);
    *reinterpret_cast<float4*>(&out[(size_t)row*NROWS + t*4]) = ov;
}

// ---------------- launch ----------------
extern "C" void kernel_launch(void* const* d_in, const int* in_sizes, int n_in,
                              void* d_out, int out_size){
    const float* adj      = (const float*)d_in[0];
    const float* adj_mean = (const float*)d_in[1];
    const float* W        = (const float*)d_in[2];
    const float* a        = (const float*)d_in[3];
    const float* gamma1   = (const float*)d_in[4];
    const float* beta1    = (const float*)d_in[5];
    const float* gamma2   = (const float*)d_in[6];
    const float* beta2    = (const float*)d_in[7];
    const float* gamma3   = (const float*)d_in[8];
    const float* beta3    = (const float*)d_in[9];
    float* out = (float*)d_out;

    cudaFuncSetAttribute(k_gemm, cudaFuncAttributeMaxDynamicSharedMemorySize, SMEM_TOT);

    k_zero    <<<1, 128>>>();
    k_colstats<<<4096, 256>>>(adj);
    k_fold1   <<<1, 256>>>(W, gamma1, beta1);
    k_gemm    <<<MROWS/128, 128, SMEM_TOT>>>();
    k_fold2   <<<1, 64>>>(gamma2, beta2);
    k_zpass   <<<2048, 256>>>(a);
    k_fold3   <<<1, 1>>>(gamma3, beta3);
    k_softmax <<<NROWS, 256>>>(adj_mean, out);
}